// round 12
// baseline (speedup 1.0000x reference)
#include <cuda_runtime.h>
#include <cuda_fp16.h>
#include <mma.h>
#include <math.h>
#include <stdint.h>

using namespace nvcuda;

#define BATCH 16
#define SEQ   2048
#define HD    128

// ---------------- scratch (__device__ globals) -----------------------------
__device__ __half g_Eh[(size_t)BATCH * SEQ * SEQ];   // 128 MB exp scores (fp16)
__device__ float  g_colsum[BATCH * SEQ];
__device__ int    g_mask_is_u8;
__device__ __half g_Qh[BATCH * SEQ * HD];
__device__ __half g_Kh[BATCH * SEQ * HD];
__device__ __half g_Vh[BATCH * SEQ * HD];            // V / colsum, fp16

// ---------------- cp.async helpers -----------------------------------------
__device__ __forceinline__ void cp16(void* smem_dst, const void* gsrc) {
    uint32_t s = (uint32_t)__cvta_generic_to_shared(smem_dst);
    asm volatile("cp.async.cg.shared.global [%0], [%1], 16;" :: "r"(s), "l"(gsrc));
}
__device__ __forceinline__ void cp_commit() {
    asm volatile("cp.async.commit_group;" ::: "memory");
}
template<int N> __device__ __forceinline__ void cp_wait() {
    asm volatile("cp.async.wait_group %0;" :: "n"(N) : "memory");
}

// ---------------- P1: Q/K -> fp16, zero colsum, detect mask dtype ----------
__global__ void prologue_kernel(const float4* __restrict__ Q,
                                const float4* __restrict__ K,
                                const int* __restrict__ mask_i) {
    const int n4 = BATCH * SEQ * HD / 4;
    int i = blockIdx.x * 256 + threadIdx.x;
    if (i < n4) {
        float4 v = Q[i];
        __half2* d = reinterpret_cast<__half2*>(g_Qh);
        d[2 * i]     = __floats2half2_rn(v.x, v.y);
        d[2 * i + 1] = __floats2half2_rn(v.z, v.w);
    } else {
        int j = i - n4;
        float4 v = K[j];
        __half2* d = reinterpret_cast<__half2*>(g_Kh);
        d[2 * j]     = __floats2half2_rn(v.x, v.y);
        d[2 * j + 1] = __floats2half2_rn(v.z, v.w);
    }
    if (i < BATCH * SEQ) g_colsum[i] = 0.0f;
    // int32 bool mask -> words in {0,1}; u8 mask read as int32 -> bytes packed
    if (i < 16384) { if ((unsigned)mask_i[i] > 1u) g_mask_is_u8 = 1; }
}

// ---------------- P2: Vh = fp16(V / colsum), same [b][k][d] layout ----------
__global__ void scale_v_kernel(const float4* __restrict__ V) {
    int i = blockIdx.x * blockDim.x + threadIdx.x;   // float4 index
    int row = i >> 5;                                // (b*SEQ + k)
    float inv = 1.0f / g_colsum[row];
    float4 v = V[i];
    __half2* dst = reinterpret_cast<__half2*>(g_Vh);
    dst[i * 2 + 0] = __floats2half2_rn(v.x * inv, v.y * inv);
    dst[i * 2 + 1] = __floats2half2_rn(v.z * inv, v.w * inv);
}

// ---------------------------------------------------------------------------
// K1: Eh[b,q,k] = half(exp( mask ? 1e-9 : (Q.K^T)/sqrt(D) ))
//     colsum[b,k] += sum_q float(Eh)        (denominator matches numerators)
// Tile 128(q) x 128(k). Epilogue: 4 k-cols/thread, 2 rows/iteration with
// both mask loads issued up front (MLP=2), 8B E stores.
// ---------------------------------------------------------------------------
constexpr int BM1 = 128, BN1 = 128;
constexpr int LD1 = 136;                        // halves; 272B rows
constexpr int QS_H   = BM1 * LD1;               // 17408 halves
constexpr int SMEM1  = 2 * QS_H * 2;            // Q + K tiles = 69632 B
constexpr int C_LD   = 132;                     // fp32 staging stride

__global__ __launch_bounds__(256, 2) void qk_exp_kernel(const void* __restrict__ mask)
{
    extern __shared__ __half hsm[];
    __shared__ float csum[BN1];
    __half* Qs = hsm;
    __half* Ks = hsm + QS_H;

    const int b  = blockIdx.z;
    const int q0 = blockIdx.y * BM1;
    const int k0 = blockIdx.x * BN1;
    const int tid  = threadIdx.x;
    const int warp = tid >> 5;
    const int warp_m = warp >> 2;   // 0..1 -> 64 q rows
    const int warp_n = warp & 3;    // 0..3 -> 32 k cols

    const __half* Qb = g_Qh + ((size_t)b * SEQ + q0) * HD;
    const __half* Kb = g_Kh + ((size_t)b * SEQ + k0) * HD;

    #pragma unroll
    for (int it = 0; it < 8; it++) {
        int idx = tid + it * 256;
        int r = idx >> 4, c8 = (idx & 15) << 3;
        cp16(Qs + r * LD1 + c8, Qb + (size_t)r * HD + c8);
    }
    #pragma unroll
    for (int it = 0; it < 8; it++) {
        int idx = tid + it * 256;
        int r = idx >> 4, c8 = (idx & 15) << 3;
        cp16(Ks + r * LD1 + c8, Kb + (size_t)r * HD + c8);
    }
    cp_commit(); cp_wait<0>();
    __syncthreads();

    wmma::fragment<wmma::accumulator, 16, 16, 16, float> acc[4][2];
    #pragma unroll
    for (int i = 0; i < 4; i++)
        #pragma unroll
        for (int j = 0; j < 2; j++)
            wmma::fill_fragment(acc[i][j], 0.0f);

    #pragma unroll
    for (int kk = 0; kk < HD; kk += 16) {
        wmma::fragment<wmma::matrix_a, 16, 16, 16, __half, wmma::row_major> af[4];
        wmma::fragment<wmma::matrix_b, 16, 16, 16, __half, wmma::col_major> bf[2];
        #pragma unroll
        for (int i = 0; i < 4; i++)
            wmma::load_matrix_sync(af[i], Qs + (warp_m * 64 + i * 16) * LD1 + kk, LD1);
        #pragma unroll
        for (int j = 0; j < 2; j++)
            wmma::load_matrix_sync(bf[j], Ks + (warp_n * 32 + j * 16) * LD1 + kk, LD1);
        #pragma unroll
        for (int i = 0; i < 4; i++)
            #pragma unroll
            for (int j = 0; j < 2; j++)
                wmma::mma_sync(acc[i][j], af[i], bf[j], acc[i][j]);
    }
    __syncthreads();   // tiles dead; reuse smem for fp32 staging

    float* C = reinterpret_cast<float*>(hsm);
    #pragma unroll
    for (int i = 0; i < 4; i++)
        #pragma unroll
        for (int j = 0; j < 2; j++)
            wmma::store_matrix_sync(C + (warp_m * 64 + i * 16) * C_LD + warp_n * 32 + j * 16,
                                    acc[i][j], C_LD, wmma::mem_row_major);
    if (tid < BN1) csum[tid] = 0.0f;
    __syncthreads();

    // Epilogue: thread owns 4 k-cols c4 = (tid&31)*4; rows ra, ra+8.
    const float scale = 0.088388347648318447f;   // 1/sqrt(128)
    const size_t moff = ((size_t)b * SEQ + q0) * SEQ + k0;
    const int*           mbi = reinterpret_cast<const int*>(mask) + moff;
    const unsigned char* mb8 = reinterpret_cast<const unsigned char*>(mask) + moff;
    const bool is_u8 = (g_mask_is_u8 != 0);
    __half* Eb = g_Eh + moff;

    const int c4 = (tid & 31) * 4;
    const int r0 = tid >> 5;
    float l0 = 0.f, l1 = 0.f, l2 = 0.f, l3 = 0.f;

    #pragma unroll
    for (int it = 0; it < 8; it++) {
        int ra = it * 16 + r0;                  // rows ra and ra+8
        size_t rowA = (size_t)ra * SEQ;
        size_t rowB = rowA + (size_t)8 * SEQ;
        int a0, a1, a2, a3, b0, b1, b2, b3;
        if (is_u8) {
            uchar4 mA = *reinterpret_cast<const uchar4*>(mb8 + rowA + c4);
            uchar4 mB = *reinterpret_cast<const uchar4*>(mb8 + rowB + c4);
            a0 = mA.x; a1 = mA.y; a2 = mA.z; a3 = mA.w;
            b0 = mB.x; b1 = mB.y; b2 = mB.z; b3 = mB.w;
        } else {
            int4 mA = *reinterpret_cast<const int4*>(mbi + rowA + c4);
            int4 mB = *reinterpret_cast<const int4*>(mbi + rowB + c4);
            a0 = mA.x; a1 = mA.y; a2 = mA.z; a3 = mA.w;
            b0 = mB.x; b1 = mB.y; b2 = mB.z; b3 = mB.w;
        }
        float4 svA = *reinterpret_cast<const float4*>(&C[ra * C_LD + c4]);
        float4 svB = *reinterpret_cast<const float4*>(&C[(ra + 8) * C_LD + c4]);
        float eA0 = __expf(a0 ? 1e-9f : svA.x * scale);
        float eA1 = __expf(a1 ? 1e-9f : svA.y * scale);
        float eA2 = __expf(a2 ? 1e-9f : svA.z * scale);
        float eA3 = __expf(a3 ? 1e-9f : svA.w * scale);
        float eB0 = __expf(b0 ? 1e-9f : svB.x * scale);
        float eB1 = __expf(b1 ? 1e-9f : svB.y * scale);
        float eB2 = __expf(b2 ? 1e-9f : svB.z * scale);
        float eB3 = __expf(b3 ? 1e-9f : svB.w * scale);
        __half2 hA01 = __floats2half2_rn(eA0, eA1);
        __half2 hA23 = __floats2half2_rn(eA2, eA3);
        __half2 hB01 = __floats2half2_rn(eB0, eB1);
        __half2 hB23 = __floats2half2_rn(eB2, eB3);
        uint2 stA, stB;
        stA.x = *reinterpret_cast<uint32_t*>(&hA01);
        stA.y = *reinterpret_cast<uint32_t*>(&hA23);
        stB.x = *reinterpret_cast<uint32_t*>(&hB01);
        stB.y = *reinterpret_cast<uint32_t*>(&hB23);
        *reinterpret_cast<uint2*>(Eb + rowA + c4) = stA;
        *reinterpret_cast<uint2*>(Eb + rowB + c4) = stB;
        // denominator = sum of the half-rounded numerators
        l0 += __low2float(hA01) + __low2float(hB01);
        l1 += __high2float(hA01) + __high2float(hB01);
        l2 += __low2float(hA23) + __low2float(hB23);
        l3 += __high2float(hA23) + __high2float(hB23);
    }
    atomicAdd(&csum[c4 + 0], l0);
    atomicAdd(&csum[c4 + 1], l1);
    atomicAdd(&csum[c4 + 2], l2);
    atomicAdd(&csum[c4 + 3], l3);
    __syncthreads();
    if (tid < BN1) atomicAdd(&g_colsum[b * SEQ + k0 + tid], csum[tid]);
}

// ---------------------------------------------------------------------------
// K2: out[b,q,d] = sum_k Eh[b,q,k] * Vh[b,k,d]   (Vh pre-scaled by 1/colsum)
// Tile 128(q) x 128(d), K chunks of 64, 3-stage cp.async, 8 warps 64x32.
// ---------------------------------------------------------------------------
constexpr int BM2 = 128, BK2 = 64;
constexpr int LDE2 = 72;                         // halves
constexpr int LDV2 = 136;                        // halves
constexpr int ST2_H  = BM2 * LDE2 + BK2 * LDV2;  // 17920 halves per stage
constexpr int NSTG2  = 3;
constexpr int SMEM2  = ST2_H * NSTG2 * 2;        // 107520 B

__global__ __launch_bounds__(256, 2) void pv_kernel(float* __restrict__ out)
{
    extern __shared__ __half hsm[];

    const int b  = blockIdx.y;
    const int q0 = blockIdx.x * BM2;
    const int tid  = threadIdx.x;
    const int warp = tid >> 5;
    const int warp_m = warp >> 2;   // 0..1 -> 64 q rows
    const int warp_n = warp & 3;    // 0..3 -> 32 d cols

    const __half* Eb = g_Eh + ((size_t)b * SEQ + q0) * SEQ;
    const __half* Vb = g_Vh + (size_t)b * SEQ * HD;

    wmma::fragment<wmma::accumulator, 16, 16, 16, float> acc[4][2];
    #pragma unroll
    for (int i = 0; i < 4; i++)
        #pragma unroll
        for (int j = 0; j < 2; j++)
            wmma::fill_fragment(acc[i][j], 0.0f);

    auto load_stage = [&](int s, int kc) {
        __half* Es = hsm + s * ST2_H;
        __half* Vs = Es + BM2 * LDE2;
        #pragma unroll
        for (int it = 0; it < 4; it++) {               // E 128 x 64 halves
            int idx = tid + it * 256;
            int r = idx >> 3, c8 = (idx & 7) << 3;
            cp16(Es + r * LDE2 + c8, Eb + (size_t)r * SEQ + kc + c8);
        }
        #pragma unroll
        for (int it = 0; it < 4; it++) {               // V 64 x 128 halves
            int idx = tid + it * 256;
            int r = idx >> 4, c8 = (idx & 15) << 3;
            cp16(Vs + r * LDV2 + c8, Vb + (size_t)(kc + r) * HD + c8);
        }
    };

    const int NC = SEQ / BK2;                          // 32 chunks
    load_stage(0, 0); cp_commit();
    load_stage(1, BK2); cp_commit();
    for (int c = 0; c < NC; c++) {
        if (c + 2 < NC) { load_stage((c + 2) % NSTG2, (c + 2) * BK2); cp_commit(); cp_wait<2>(); }
        else if (c + 1 < NC) { cp_wait<1>(); }
        else { cp_wait<0>(); }
        __syncthreads();

        __half* Es = hsm + (c % NSTG2) * ST2_H;
        __half* Vs = Es + BM2 * LDE2;
        #pragma unroll
        for (int kk = 0; kk < BK2; kk += 16) {
            wmma::fragment<wmma::matrix_a, 16, 16, 16, __half, wmma::row_major> af[4];
            wmma::fragment<wmma::matrix_b, 16, 16, 16, __half, wmma::row_major> bf[2];
            #pragma unroll
            for (int i = 0; i < 4; i++)
                wmma::load_matrix_sync(af[i], Es + (warp_m * 64 + i * 16) * LDE2 + kk, LDE2);
            #pragma unroll
            for (int j = 0; j < 2; j++)
                wmma::load_matrix_sync(bf[j], Vs + kk * LDV2 + warp_n * 32 + j * 16, LDV2);
            #pragma unroll
            for (int i = 0; i < 4; i++)
                #pragma unroll
                for (int j = 0; j < 2; j++)
                    wmma::mma_sync(acc[i][j], af[i], bf[j], acc[i][j]);
        }
        __syncthreads();   // protects stage (c)%NSTG2 before its rewrite
    }

    #pragma unroll
    for (int i = 0; i < 4; i++)
        #pragma unroll
        for (int j = 0; j < 2; j++) {
            float* dst = out + ((size_t)b * SEQ + q0 + warp_m * 64 + i * 16) * HD
                             + warp_n * 32 + j * 16;
            wmma::store_matrix_sync(dst, acc[i][j], HD, wmma::mem_row_major);
        }
}

// ---------------------------------------------------------------------------
extern "C" void kernel_launch(void* const* d_in, const int* in_sizes, int n_in,
                              void* d_out, int out_size) {
    const float* Q = (const float*)d_in[0];
    const float* K = (const float*)d_in[1];
    const float* V = (const float*)d_in[2];
    const void*  mask = d_in[3];
    float* out = (float*)d_out;

    cudaFuncSetAttribute(qk_exp_kernel, cudaFuncAttributeMaxDynamicSharedMemorySize, SMEM1);
    cudaFuncSetAttribute(pv_kernel,     cudaFuncAttributeMaxDynamicSharedMemorySize, SMEM2);

    const int n4 = BATCH * SEQ * HD / 4;   // float4 count per tensor

    prologue_kernel<<<2 * n4 / 256, 256>>>((const float4*)Q, (const float4*)K, (const int*)mask);
    qk_exp_kernel<<<dim3(SEQ / BN1, SEQ / BM1, BATCH), 256, SMEM1>>>(mask);
    scale_v_kernel<<<n4 / 256, 256>>>((const float4*)V);
    pv_kernel<<<dim3(SEQ / BM2, BATCH), 256, SMEM2>>>(out);
}

// round 13
// speedup vs baseline: 1.2295x; 1.2295x over previous
#include <cuda_runtime.h>
#include <cuda_fp16.h>
#include <mma.h>
#include <math.h>
#include <stdint.h>

using namespace nvcuda;

#define BATCH 16
#define SEQ   2048
#define HD    128

// ---------------- scratch (__device__ globals) -----------------------------
__device__ __half g_Eh[(size_t)BATCH * SEQ * SEQ];   // 128 MB exp scores (fp16)
__device__ float  g_colsum[BATCH * SEQ];
__device__ int    g_mask_is_u8;
__device__ __half g_Qh[BATCH * SEQ * HD];
__device__ __half g_Kh[BATCH * SEQ * HD];
__device__ __half g_Vh[BATCH * SEQ * HD];            // V / colsum, fp16

// ---------------- cp.async helpers -----------------------------------------
__device__ __forceinline__ void cp16(void* smem_dst, const void* gsrc) {
    uint32_t s = (uint32_t)__cvta_generic_to_shared(smem_dst);
    asm volatile("cp.async.cg.shared.global [%0], [%1], 16;" :: "r"(s), "l"(gsrc));
}
__device__ __forceinline__ void cp_commit() {
    asm volatile("cp.async.commit_group;" ::: "memory");
}
template<int N> __device__ __forceinline__ void cp_wait() {
    asm volatile("cp.async.wait_group %0;" :: "n"(N) : "memory");
}

// ---------------- P1: Q/K -> fp16, zero colsum, detect mask dtype ----------
__global__ void prologue_kernel(const float4* __restrict__ Q,
                                const float4* __restrict__ K,
                                const int* __restrict__ mask_i) {
    const int n4 = BATCH * SEQ * HD / 4;
    int i = blockIdx.x * 256 + threadIdx.x;
    if (i < n4) {
        float4 v = Q[i];
        __half2* d = reinterpret_cast<__half2*>(g_Qh);
        d[2 * i]     = __floats2half2_rn(v.x, v.y);
        d[2 * i + 1] = __floats2half2_rn(v.z, v.w);
    } else {
        int j = i - n4;
        float4 v = K[j];
        __half2* d = reinterpret_cast<__half2*>(g_Kh);
        d[2 * j]     = __floats2half2_rn(v.x, v.y);
        d[2 * j + 1] = __floats2half2_rn(v.z, v.w);
    }
    if (i < BATCH * SEQ) g_colsum[i] = 0.0f;
    // int32 bool mask -> words in {0,1}; u8 mask read as int32 -> bytes packed
    if (i < 16384) { if ((unsigned)mask_i[i] > 1u) g_mask_is_u8 = 1; }
}

// ---------------- P2: Vh = fp16(V / colsum), same [b][k][d] layout ----------
__global__ void scale_v_kernel(const float4* __restrict__ V) {
    int i = blockIdx.x * blockDim.x + threadIdx.x;   // float4 index
    int row = i >> 5;                                // (b*SEQ + k)
    float inv = 1.0f / g_colsum[row];
    float4 v = V[i];
    __half2* dst = reinterpret_cast<__half2*>(g_Vh);
    dst[i * 2 + 0] = __floats2half2_rn(v.x * inv, v.y * inv);
    dst[i * 2 + 1] = __floats2half2_rn(v.z * inv, v.w * inv);
}

// ---------------------------------------------------------------------------
// K1: Eh[b,q,k] = half(exp( mask ? 1e-9 : (Q.K^T)/sqrt(D) ))
//     colsum[b,k] += sum_q float(Eh)        (denominator matches numerators)
// Tile 128(q) x 128(k). Epilogue: 4 k-cols/thread, vectorized mask read +
// 8B E store, smem-reduced colsum.   (R10 version — local optimum.)
// ---------------------------------------------------------------------------
constexpr int BM1 = 128, BN1 = 128;
constexpr int LD1 = 136;                        // halves; 272B rows
constexpr int QS_H   = BM1 * LD1;               // 17408 halves
constexpr int SMEM1  = 2 * QS_H * 2;            // Q + K tiles = 69632 B
constexpr int C_LD   = 132;                     // fp32 staging stride

__global__ __launch_bounds__(256, 2) void qk_exp_kernel(const void* __restrict__ mask)
{
    extern __shared__ __half hsm[];
    __shared__ float csum[BN1];
    __half* Qs = hsm;
    __half* Ks = hsm + QS_H;

    const int b  = blockIdx.z;
    const int q0 = blockIdx.y * BM1;
    const int k0 = blockIdx.x * BN1;
    const int tid  = threadIdx.x;
    const int warp = tid >> 5;
    const int warp_m = warp >> 2;   // 0..1 -> 64 q rows
    const int warp_n = warp & 3;    // 0..3 -> 32 k cols

    const __half* Qb = g_Qh + ((size_t)b * SEQ + q0) * HD;
    const __half* Kb = g_Kh + ((size_t)b * SEQ + k0) * HD;

    #pragma unroll
    for (int it = 0; it < 8; it++) {
        int idx = tid + it * 256;
        int r = idx >> 4, c8 = (idx & 15) << 3;
        cp16(Qs + r * LD1 + c8, Qb + (size_t)r * HD + c8);
    }
    #pragma unroll
    for (int it = 0; it < 8; it++) {
        int idx = tid + it * 256;
        int r = idx >> 4, c8 = (idx & 15) << 3;
        cp16(Ks + r * LD1 + c8, Kb + (size_t)r * HD + c8);
    }
    cp_commit(); cp_wait<0>();
    __syncthreads();

    wmma::fragment<wmma::accumulator, 16, 16, 16, float> acc[4][2];
    #pragma unroll
    for (int i = 0; i < 4; i++)
        #pragma unroll
        for (int j = 0; j < 2; j++)
            wmma::fill_fragment(acc[i][j], 0.0f);

    #pragma unroll
    for (int kk = 0; kk < HD; kk += 16) {
        wmma::fragment<wmma::matrix_a, 16, 16, 16, __half, wmma::row_major> af[4];
        wmma::fragment<wmma::matrix_b, 16, 16, 16, __half, wmma::col_major> bf[2];
        #pragma unroll
        for (int i = 0; i < 4; i++)
            wmma::load_matrix_sync(af[i], Qs + (warp_m * 64 + i * 16) * LD1 + kk, LD1);
        #pragma unroll
        for (int j = 0; j < 2; j++)
            wmma::load_matrix_sync(bf[j], Ks + (warp_n * 32 + j * 16) * LD1 + kk, LD1);
        #pragma unroll
        for (int i = 0; i < 4; i++)
            #pragma unroll
            for (int j = 0; j < 2; j++)
                wmma::mma_sync(acc[i][j], af[i], bf[j], acc[i][j]);
    }
    __syncthreads();   // tiles dead; reuse smem for fp32 staging

    float* C = reinterpret_cast<float*>(hsm);
    #pragma unroll
    for (int i = 0; i < 4; i++)
        #pragma unroll
        for (int j = 0; j < 2; j++)
            wmma::store_matrix_sync(C + (warp_m * 64 + i * 16) * C_LD + warp_n * 32 + j * 16,
                                    acc[i][j], C_LD, wmma::mem_row_major);
    if (tid < BN1) csum[tid] = 0.0f;
    __syncthreads();

    // Epilogue: thread owns 4 k-cols c4 = (tid&31)*4; rows r = it*8 + (tid>>5).
    const float scale = 0.088388347648318447f;   // 1/sqrt(128)
    const size_t moff = ((size_t)b * SEQ + q0) * SEQ + k0;
    const int*           mbi = reinterpret_cast<const int*>(mask) + moff;
    const unsigned char* mb8 = reinterpret_cast<const unsigned char*>(mask) + moff;
    const bool is_u8 = (g_mask_is_u8 != 0);
    __half* Eb = g_Eh + moff;

    const int c4 = (tid & 31) * 4;
    const int r0 = tid >> 5;
    float l0 = 0.f, l1 = 0.f, l2 = 0.f, l3 = 0.f;

    #pragma unroll
    for (int it = 0; it < 16; it++) {
        int r = it * 8 + r0;
        size_t row = (size_t)r * SEQ;
        float4 sv = *reinterpret_cast<const float4*>(&C[r * C_LD + c4]);
        int m0, m1, m2, m3;
        if (is_u8) {
            uchar4 mu = *reinterpret_cast<const uchar4*>(mb8 + row + c4);
            m0 = mu.x; m1 = mu.y; m2 = mu.z; m3 = mu.w;
        } else {
            int4 mi = *reinterpret_cast<const int4*>(mbi + row + c4);
            m0 = mi.x; m1 = mi.y; m2 = mi.z; m3 = mi.w;
        }
        float e0 = __expf(m0 ? 1e-9f : sv.x * scale);
        float e1 = __expf(m1 ? 1e-9f : sv.y * scale);
        float e2 = __expf(m2 ? 1e-9f : sv.z * scale);
        float e3 = __expf(m3 ? 1e-9f : sv.w * scale);
        __half2 h01 = __floats2half2_rn(e0, e1);
        __half2 h23 = __floats2half2_rn(e2, e3);
        uint2 st;
        st.x = *reinterpret_cast<uint32_t*>(&h01);
        st.y = *reinterpret_cast<uint32_t*>(&h23);
        *reinterpret_cast<uint2*>(Eb + row + c4) = st;
        // denominator = sum of the half-rounded numerators
        l0 += __low2float(h01); l1 += __high2float(h01);
        l2 += __low2float(h23); l3 += __high2float(h23);
    }
    atomicAdd(&csum[c4 + 0], l0);
    atomicAdd(&csum[c4 + 1], l1);
    atomicAdd(&csum[c4 + 2], l2);
    atomicAdd(&csum[c4 + 3], l3);
    __syncthreads();
    if (tid < BN1) atomicAdd(&g_colsum[b * SEQ + k0 + tid], csum[tid]);
}

// ---------------------------------------------------------------------------
// K2: out[b,q,d] = sum_k Eh[b,q,k] * Vh[b,k,d]   (Vh pre-scaled by 1/colsum)
// Tile 128(q) x 128(d), K chunks of 64, 3-stage cp.async pipeline with ONE
// __syncthreads per chunk: wait(stage c) -> sync -> issue load(c+2) -> MMA(c).
// Safe: a warp passes iteration c's sync only after finishing MMA(c-1), and
// load(c+2) overwrites exactly the stage MMA'd at c-1.
// ---------------------------------------------------------------------------
constexpr int BM2 = 128, BK2 = 64;
constexpr int LDE2 = 72;                         // halves
constexpr int LDV2 = 136;                        // halves
constexpr int ST2_H  = BM2 * LDE2 + BK2 * LDV2;  // 17920 halves per stage
constexpr int NSTG2  = 3;
constexpr int SMEM2  = ST2_H * NSTG2 * 2;        // 107520 B

__global__ __launch_bounds__(256, 2) void pv_kernel(float* __restrict__ out)
{
    extern __shared__ __half hsm[];

    const int b  = blockIdx.y;
    const int q0 = blockIdx.x * BM2;
    const int tid  = threadIdx.x;
    const int warp = tid >> 5;
    const int warp_m = warp >> 2;   // 0..1 -> 64 q rows
    const int warp_n = warp & 3;    // 0..3 -> 32 d cols

    const __half* Eb = g_Eh + ((size_t)b * SEQ + q0) * SEQ;
    const __half* Vb = g_Vh + (size_t)b * SEQ * HD;

    wmma::fragment<wmma::accumulator, 16, 16, 16, float> acc[4][2];
    #pragma unroll
    for (int i = 0; i < 4; i++)
        #pragma unroll
        for (int j = 0; j < 2; j++)
            wmma::fill_fragment(acc[i][j], 0.0f);

    auto load_stage = [&](int s, int kc) {
        __half* Es = hsm + s * ST2_H;
        __half* Vs = Es + BM2 * LDE2;
        #pragma unroll
        for (int it = 0; it < 4; it++) {               // E 128 x 64 halves
            int idx = tid + it * 256;
            int r = idx >> 3, c8 = (idx & 7) << 3;
            cp16(Es + r * LDE2 + c8, Eb + (size_t)r * SEQ + kc + c8);
        }
        #pragma unroll
        for (int it = 0; it < 4; it++) {               // V 64 x 128 halves
            int idx = tid + it * 256;
            int r = idx >> 4, c8 = (idx & 15) << 3;
            cp16(Vs + r * LDV2 + c8, Vb + (size_t)(kc + r) * HD + c8);
        }
        cp_commit();
    };

    const int NC = SEQ / BK2;                          // 32 chunks
    load_stage(0, 0);
    load_stage(1, BK2);
    for (int c = 0; c < NC; c++) {
        if (c < NC - 1) cp_wait<1>(); else cp_wait<0>();
        __syncthreads();
        if (c + 2 < NC) load_stage((c + 2) % NSTG2, (c + 2) * BK2);

        __half* Es = hsm + (c % NSTG2) * ST2_H;
        __half* Vs = Es + BM2 * LDE2;
        #pragma unroll
        for (int kk = 0; kk < BK2; kk += 16) {
            wmma::fragment<wmma::matrix_a, 16, 16, 16, __half, wmma::row_major> af[4];
            wmma::fragment<wmma::matrix_b, 16, 16, 16, __half, wmma::row_major> bf[2];
            #pragma unroll
            for (int i = 0; i < 4; i++)
                wmma::load_matrix_sync(af[i], Es + (warp_m * 64 + i * 16) * LDE2 + kk, LDE2);
            #pragma unroll
            for (int j = 0; j < 2; j++)
                wmma::load_matrix_sync(bf[j], Vs + kk * LDV2 + warp_n * 32 + j * 16, LDV2);
            #pragma unroll
            for (int i = 0; i < 4; i++)
                #pragma unroll
                for (int j = 0; j < 2; j++)
                    wmma::mma_sync(acc[i][j], af[i], bf[j], acc[i][j]);
        }
        // no trailing sync: next iteration's barrier provides the guard
    }

    #pragma unroll
    for (int i = 0; i < 4; i++)
        #pragma unroll
        for (int j = 0; j < 2; j++) {
            float* dst = out + ((size_t)b * SEQ + q0 + warp_m * 64 + i * 16) * HD
                             + warp_n * 32 + j * 16;
            wmma::store_matrix_sync(dst, acc[i][j], HD, wmma::mem_row_major);
        }
}

// ---------------------------------------------------------------------------
extern "C" void kernel_launch(void* const* d_in, const int* in_sizes, int n_in,
                              void* d_out, int out_size) {
    const float* Q = (const float*)d_in[0];
    const float* K = (const float*)d_in[1];
    const float* V = (const float*)d_in[2];
    const void*  mask = d_in[3];
    float* out = (float*)d_out;

    cudaFuncSetAttribute(qk_exp_kernel, cudaFuncAttributeMaxDynamicSharedMemorySize, SMEM1);
    cudaFuncSetAttribute(pv_kernel,     cudaFuncAttributeMaxDynamicSharedMemorySize, SMEM2);

    const int n4 = BATCH * SEQ * HD / 4;   // float4 count per tensor

    prologue_kernel<<<2 * n4 / 256, 256>>>((const float4*)Q, (const float4*)K, (const int*)mask);
    qk_exp_kernel<<<dim3(SEQ / BN1, SEQ / BM1, BATCH), 256, SMEM1>>>(mask);
    scale_v_kernel<<<n4 / 256, 256>>>((const float4*)V);
    pv_kernel<<<dim3(SEQ / BM2, BATCH), 256, SMEM2>>>(out);
}